// round 1
// baseline (speedup 1.0000x reference)
#include <cuda_runtime.h>
#include <math.h>

#define BB 64
#define LL 128
#define DD 200
#define MPP 20
#define ATTN 50
#define OC 83

// ---------------- scratch (no cudaMalloc allowed) ----------------
__device__ __align__(16) float g_e_rt[BB * LL * ATTN];
__device__ __align__(16) float g_e_lt[BB * LL * ATTN];
__device__ __align__(16) float g_att_lt[BB * LL * DD];
__device__ int g_pos[BB * LL];

// packed fp32x2 FMA (Blackwell FFMA2; ptxas will not auto-fuse, PTX form required)
__device__ __forceinline__ float2 ffma2(float2 a, float2 b, float2 c) {
    float2 d;
    asm("{\n\t"
        ".reg .b64 ra, rb, rc, rd;\n\t"
        "mov.b64 ra, {%2, %3};\n\t"
        "mov.b64 rb, {%4, %5};\n\t"
        "mov.b64 rc, {%6, %7};\n\t"
        "fma.rn.f32x2 rd, ra, rb, rc;\n\t"
        "mov.b64 {%0, %1}, rd;\n\t"
        "}"
        : "=f"(d.x), "=f"(d.y)
        : "f"(a.x), "f"(a.y), "f"(b.x), "f"(b.y), "f"(c.x), "f"(c.y));
    return d;
}

// ================= full match: out cols [0,21) =================
__global__ __launch_bounds__(128) void full_kernel(
        const float* __restrict__ lt, const float* __restrict__ fw,
        const float* __restrict__ bw, const float* __restrict__ wf,
        float* __restrict__ out) {
    __shared__ float hw[MPP + 1][DD];  // hw[0]=h, hw[1+m]=w_full[m]*h
    int b = blockIdx.x, tid = threadIdx.x;
    for (int idx = tid; idx < (MPP + 1) * DD; idx += 128) {
        int mm = idx / DD, d = idx - mm * DD;
        float hv = (d < DD / 2) ? fw[b * (DD / 2) + d] : bw[b * (DD / 2) + d - DD / 2];
        hw[mm][d] = (mm == 0) ? hv : wf[(mm - 1) * DD + d] * hv;
    }
    __syncthreads();
    int l = tid;
    const float4* row = (const float4*)(lt + (size_t)(b * LL + l) * DD);
    float acc[MPP + 1];
#pragma unroll
    for (int mm = 0; mm <= MPP; mm++) acc[mm] = 0.f;
    for (int d4 = 0; d4 < DD / 4; d4++) {
        float4 x = __ldg(row + d4);
        int d = d4 * 4;
#pragma unroll
        for (int mm = 0; mm <= MPP; mm++)
            acc[mm] += x.x * hw[mm][d] + x.y * hw[mm][d + 1] +
                       x.z * hw[mm][d + 2] + x.w * hw[mm][d + 3];
    }
    float* o = out + (size_t)(b * LL + l) * OC;
#pragma unroll
    for (int mm = 0; mm <= MPP; mm++) o[mm] = tanhf(acc[mm]);
}

// ================= maxpool match: out cols [21,41) =================
// One CTA per (b,m): S = (lt .* w_m) @ rt^T [128x128, K=200], rowwise max, tanh.
// tanh(max) == max(tanh) since tanh monotone.
__global__ __launch_bounds__(256) void maxpool_kernel(
        const float* __restrict__ lt, const float* __restrict__ rt,
        const float* __restrict__ w, float* __restrict__ out) {
    __shared__ float As[8][128];
    __shared__ float Bs[8][128];
    __shared__ float red[128][16];
    int b = blockIdx.x, m = blockIdx.y;
    int tid = threadIdx.x;
    int tx = tid & 15, ty = tid >> 4;
    int lrow = tid >> 1, kq = tid & 1;
    const float4* ltp = (const float4*)(lt + (size_t)(b * LL + lrow) * DD);
    const float4* rtp = (const float4*)(rt + (size_t)(b * LL + lrow) * DD);
    const float4* wp = (const float4*)(w + (size_t)m * DD);
    float2 acc[8][4];
#pragma unroll
    for (int i = 0; i < 8; i++)
#pragma unroll
        for (int j = 0; j < 4; j++) acc[i][j] = make_float2(0.f, 0.f);

    for (int kc = 0; kc < DD / 8; kc++) {
        float4 av = __ldg(ltp + kc * 2 + kq);
        float4 wv = __ldg(wp + kc * 2 + kq);
        float4 bv = __ldg(rtp + kc * 2 + kq);
        int kb = kq * 4;
        As[kb + 0][lrow] = av.x * wv.x;
        As[kb + 1][lrow] = av.y * wv.y;
        As[kb + 2][lrow] = av.z * wv.z;
        As[kb + 3][lrow] = av.w * wv.w;
        Bs[kb + 0][lrow] = bv.x;
        Bs[kb + 1][lrow] = bv.y;
        Bs[kb + 2][lrow] = bv.z;
        Bs[kb + 3][lrow] = bv.w;
        __syncthreads();
#pragma unroll
        for (int k = 0; k < 8; k++) {
            float a[8];
#pragma unroll
            for (int i = 0; i < 8; i++) a[i] = As[k][ty + 16 * i];
#pragma unroll
            for (int j = 0; j < 4; j++) {
                float2 bv2 = *(const float2*)&Bs[k][2 * tx + 32 * j];
#pragma unroll
                for (int i = 0; i < 8; i++)
                    acc[i][j] = ffma2(make_float2(a[i], a[i]), bv2, acc[i][j]);
            }
        }
        __syncthreads();
    }
#pragma unroll
    for (int i = 0; i < 8; i++) {
        float mx = -3.4e38f;
#pragma unroll
        for (int j = 0; j < 4; j++) mx = fmaxf(mx, fmaxf(acc[i][j].x, acc[i][j].y));
        red[ty + 16 * i][tx] = mx;
    }
    __syncthreads();
    if (tid < 128) {
        float mx = red[tid][0];
#pragma unroll
        for (int t = 1; t < 16; t++) mx = fmaxf(mx, red[tid][t]);
        out[(size_t)(b * LL + tid) * OC + 21 + m] = tanhf(mx);
    }
}

// ================= attention projections: e_rt, e_lt =================
__global__ __launch_bounds__(256) void proj_kernel(
        const float* __restrict__ lt, const float* __restrict__ rt,
        const float* __restrict__ w1, const float* __restrict__ w2,
        const float* __restrict__ diag) {
    extern __shared__ float sm[];
    float* w1s = sm;                 // DD*ATTN
    float* w2s = sm + DD * ATTN;     // DD*ATTN
    float* dg = sm + 2 * DD * ATTN;  // ATTN
    int b = blockIdx.x, tid = threadIdx.x;
    for (int i = tid; i < DD * ATTN; i += 256) {
        w1s[i] = w1[i];
        w2s[i] = w2[i];
    }
    if (tid < ATTN) dg[tid] = diag[tid];
    __syncthreads();
    int is_rt = (tid < 128) ? 1 : 0;
    int l = tid & 127;
    const float* base = is_rt ? rt : lt;
    const float4* row = (const float4*)(base + (size_t)(b * LL + l) * DD);
    const float* ws = is_rt ? w1s : w2s;
    float2 acc[ATTN / 2];
#pragma unroll
    for (int a = 0; a < ATTN / 2; a++) acc[a] = make_float2(0.f, 0.f);
    for (int d4 = 0; d4 < DD / 4; d4++) {
        float4 x = __ldg(row + d4);
#pragma unroll
        for (int c = 0; c < 4; c++) {
            float xc = (c == 0) ? x.x : (c == 1) ? x.y : (c == 2) ? x.z : x.w;
            const float2* wr = (const float2*)(ws + (d4 * 4 + c) * ATTN);
            float2 x2 = make_float2(xc, xc);
#pragma unroll
            for (int a = 0; a < ATTN / 2; a++) acc[a] = ffma2(x2, wr[a], acc[a]);
        }
    }
    float* e = (is_rt ? g_e_rt : g_e_lt) + (size_t)(b * LL + l) * ATTN;
#pragma unroll
    for (int a = 0; a < ATTN / 2; a++) {
        float v0 = tanhf(acc[a].x), v1 = tanhf(acc[a].y);
        if (is_rt) {
            v0 *= dg[2 * a];
            v1 *= dg[2 * a + 1];
        }
        e[2 * a] = v0;
        e[2 * a + 1] = v1;
    }
}

// ================= attentive match core: logits + softmax + att_lt =================
// smem layout (floats): Z[128*129] | ers[128*50] | eltsT[50*128] (reused as Bs[8*128] in phase 2)
__global__ __launch_bounds__(256) void attn_kernel(const float* __restrict__ lt) {
    extern __shared__ float sm[];
    float* Z = sm;                      // 16512
    float* ers = sm + 16512;            // 6400
    float* eltsT = sm + 16512 + 6400;   // 6400 (phase1), Bs aliases this (phase2)
    float* Bs = eltsT;
    int b = blockIdx.x, tid = threadIdx.x;
    int tx = tid & 15, ty = tid >> 4;

    for (int i = tid; i < LL * ATTN; i += 256) {
        ers[i] = g_e_rt[(size_t)b * LL * ATTN + i];
        int l = i / ATTN, a = i - l * ATTN;
        eltsT[a * LL + l] = g_e_lt[(size_t)b * LL * ATTN + i];
    }
    __syncthreads();

    // phase 1: Z[r][c] = sum_a ers[r][a] * eltsT[a][c]
    {
        float2 acc[8][4];
#pragma unroll
        for (int i = 0; i < 8; i++)
#pragma unroll
            for (int j = 0; j < 4; j++) acc[i][j] = make_float2(0.f, 0.f);
        for (int k = 0; k < ATTN; k++) {
            float a[8];
#pragma unroll
            for (int i = 0; i < 8; i++) a[i] = ers[(ty + 16 * i) * ATTN + k];
#pragma unroll
            for (int j = 0; j < 4; j++) {
                float2 bv = *(const float2*)&eltsT[k * LL + 2 * tx + 32 * j];
#pragma unroll
                for (int i = 0; i < 8; i++)
                    acc[i][j] = ffma2(make_float2(a[i], a[i]), bv, acc[i][j]);
            }
        }
#pragma unroll
        for (int i = 0; i < 8; i++)
#pragma unroll
            for (int j = 0; j < 4; j++) {
                int r = ty + 16 * i, c = 2 * tx + 32 * j;
                Z[r * 129 + c] = acc[i][j].x;
                Z[r * 129 + c + 1] = acc[i][j].y;
            }
    }
    __syncthreads();

    // softmax over each row of Z
    if (tid < 128) {
        float* zr = Z + tid * 129;
        float mx = zr[0];
        for (int k = 1; k < 128; k++) mx = fmaxf(mx, zr[k]);
        float s = 0.f;
        for (int k = 0; k < 128; k++) {
            float e = expf(zr[k] - mx);
            zr[k] = e;
            s += e;
        }
        float inv = 1.f / s;
        for (int k = 0; k < 128; k++) zr[k] *= inv;
    }
    __syncthreads();

    // phase 2: att_lt[r][d] = sum_ll Z[r][ll] * lt[ll][d]  (d in two 128-wide blocks)
    for (int nb = 0; nb < 2; nb++) {
        float2 acc[8][4];
#pragma unroll
        for (int i = 0; i < 8; i++)
#pragma unroll
            for (int j = 0; j < 4; j++) acc[i][j] = make_float2(0.f, 0.f);
        for (int kc = 0; kc < 16; kc++) {
            int k = tid >> 5;
            int c4 = tid & 31;
            int gcol = nb * 128 + c4 * 4;
            int grow = kc * 8 + k;
            float4 v = make_float4(0.f, 0.f, 0.f, 0.f);
            if (gcol + 3 < DD)
                v = __ldg((const float4*)(lt + (size_t)(b * LL + grow) * DD + gcol));
            *(float4*)&Bs[k * 128 + c4 * 4] = v;
            __syncthreads();
#pragma unroll
            for (int kk = 0; kk < 8; kk++) {
                float a[8];
#pragma unroll
                for (int i = 0; i < 8; i++) a[i] = Z[(ty + 16 * i) * 129 + kc * 8 + kk];
#pragma unroll
                for (int j = 0; j < 4; j++) {
                    float2 bv = *(const float2*)&Bs[kk * 128 + 2 * tx + 32 * j];
#pragma unroll
                    for (int i = 0; i < 8; i++)
                        acc[i][j] = ffma2(make_float2(a[i], a[i]), bv, acc[i][j]);
                }
            }
            __syncthreads();
        }
#pragma unroll
        for (int i = 0; i < 8; i++)
#pragma unroll
            for (int j = 0; j < 4; j++) {
                int r = ty + 16 * i;
                int d = nb * 128 + 2 * tx + 32 * j;
                if (d < DD - 1)
                    *(float2*)(g_att_lt + (size_t)(b * LL + r) * DD + d) =
                        make_float2(acc[i][j].x, acc[i][j].y);
            }
    }
}

// ================= max-attentive: argmax of normalized cosine =================
// rel[lr][ll] = (rt[lr].lt[ll]) / (||rt[lr]|| * ||lt[ll]||); ||rt|| > 0 drops out of argmax.
__global__ __launch_bounds__(256) void maxatt_kernel(
        const float* __restrict__ lt, const float* __restrict__ rt) {
    __shared__ float As[8][128];
    __shared__ float Bs[8][128];
    __shared__ float nlt[128];
    __shared__ float redv[128][16];
    __shared__ int redi[128][16];
    int b = blockIdx.x, tid = threadIdx.x;
    int tx = tid & 15, ty = tid >> 4;
    if (tid < 128) {
        const float4* p = (const float4*)(lt + (size_t)(b * LL + tid) * DD);
        float s = 0.f;
        for (int i = 0; i < DD / 4; i++) {
            float4 v = __ldg(p + i);
            s += v.x * v.x + v.y * v.y + v.z * v.z + v.w * v.w;
        }
        nlt[tid] = rsqrtf(fmaxf(s, 1e-6f));
    }
    int lrow = tid >> 1, kq = tid & 1;
    const float4* ap = (const float4*)(rt + (size_t)(b * LL + lrow) * DD);
    const float4* bp = (const float4*)(lt + (size_t)(b * LL + lrow) * DD);
    float2 acc[8][4];
#pragma unroll
    for (int i = 0; i < 8; i++)
#pragma unroll
        for (int j = 0; j < 4; j++) acc[i][j] = make_float2(0.f, 0.f);
    for (int kc = 0; kc < DD / 8; kc++) {
        float4 av = __ldg(ap + kc * 2 + kq);
        float4 bv = __ldg(bp + kc * 2 + kq);
        int kb = kq * 4;
        As[kb + 0][lrow] = av.x;
        As[kb + 1][lrow] = av.y;
        As[kb + 2][lrow] = av.z;
        As[kb + 3][lrow] = av.w;
        Bs[kb + 0][lrow] = bv.x;
        Bs[kb + 1][lrow] = bv.y;
        Bs[kb + 2][lrow] = bv.z;
        Bs[kb + 3][lrow] = bv.w;
        __syncthreads();
#pragma unroll
        for (int k = 0; k < 8; k++) {
            float a[8];
#pragma unroll
            for (int i = 0; i < 8; i++) a[i] = As[k][ty + 16 * i];
#pragma unroll
            for (int j = 0; j < 4; j++) {
                float2 bv2 = *(const float2*)&Bs[k][2 * tx + 32 * j];
#pragma unroll
                for (int i = 0; i < 8; i++)
                    acc[i][j] = ffma2(make_float2(a[i], a[i]), bv2, acc[i][j]);
            }
        }
        __syncthreads();
    }
#pragma unroll
    for (int i = 0; i < 8; i++) {
        int r = ty + 16 * i;
        float best = -3.4e38f;
        int bi = 0;
#pragma unroll
        for (int j = 0; j < 4; j++) {
            int c = 2 * tx + 32 * j;
            float v0 = acc[i][j].x * nlt[c];
            float v1 = acc[i][j].y * nlt[c + 1];
            if (v0 > best) { best = v0; bi = c; }
            if (v1 > best) { best = v1; bi = c + 1; }
        }
        redv[r][tx] = best;
        redi[r][tx] = bi;
    }
    __syncthreads();
    if (tid < 128) {
        float best = redv[tid][0];
        int bi = redi[tid][0];
#pragma unroll
        for (int t = 1; t < 16; t++) {
            float v = redv[tid][t];
            int ii = redi[tid][t];
            if (v > best || (v == best && ii < bi)) { best = v; bi = ii; }
        }
        g_pos[b * LL + tid] = bi;
    }
}

// ================= elementwise mp match (used for attentive + max-attentive) =================
// mode 0: X = g_att_lt row l, Y = reps_rt row l            -> cols [41,62)
// mode 1: X = reps_rt row l, Y = reps_lt row g_pos[b,l]     -> cols [62,83)
__global__ __launch_bounds__(128) void mp_elem_kernel(
        const float* __restrict__ reps_lt, const float* __restrict__ reps_rt,
        const float* __restrict__ w, float* __restrict__ out,
        int mode, int col_base) {
    __shared__ float wsT[DD][MPP];  // transposed for f32x2 over m
    int b = blockIdx.x, tid = threadIdx.x;
    for (int i = tid; i < DD * MPP; i += 128) {
        int d = i / MPP, m = i - d * MPP;
        wsT[d][m] = w[m * DD + d];
    }
    __syncthreads();
    int l = tid;
    const float4* xr;
    const float4* yr;
    if (mode == 0) {
        xr = (const float4*)(g_att_lt + (size_t)(b * LL + l) * DD);
        yr = (const float4*)(reps_rt + (size_t)(b * LL + l) * DD);
    } else {
        xr = (const float4*)(reps_rt + (size_t)(b * LL + l) * DD);
        int yl = g_pos[b * LL + l];
        yr = (const float4*)(reps_lt + (size_t)(b * LL + yl) * DD);
    }
    float cos_acc = 0.f;
    float2 macc[MPP / 2];
#pragma unroll
    for (int mm = 0; mm < MPP / 2; mm++) macc[mm] = make_float2(0.f, 0.f);
    for (int d4 = 0; d4 < DD / 4; d4++) {
        float4 x = __ldg(xr + d4);
        float4 y = __ldg(yr + d4);
        float p[4] = {x.x * y.x, x.y * y.y, x.z * y.z, x.w * y.w};
#pragma unroll
        for (int c = 0; c < 4; c++) {
            cos_acc += p[c];
            const float2* wr = (const float2*)&wsT[d4 * 4 + c][0];
            float2 p2 = make_float2(p[c], p[c]);
#pragma unroll
            for (int mm = 0; mm < MPP / 2; mm++) macc[mm] = ffma2(p2, wr[mm], macc[mm]);
        }
    }
    float* o = out + (size_t)(b * LL + l) * OC + col_base;
    o[0] = tanhf(cos_acc);
#pragma unroll
    for (int mm = 0; mm < MPP / 2; mm++) {
        o[1 + 2 * mm] = tanhf(macc[mm].x);
        o[2 + 2 * mm] = tanhf(macc[mm].y);
    }
}

// ================= launch =================
extern "C" void kernel_launch(void* const* d_in, const int* in_sizes, int n_in,
                              void* d_out, int out_size) {
    const float* reps_lt = (const float*)d_in[0];
    const float* reps_rt = (const float*)d_in[1];
    const float* fw_h = (const float*)d_in[2];
    const float* bw_h = (const float*)d_in[3];
    const float* w_full = (const float*)d_in[4];
    const float* w_maxpool = (const float*)d_in[5];
    const float* w_att = (const float*)d_in[6];
    const float* w_maxatt = (const float*)d_in[7];
    const float* attn_w1 = (const float*)d_in[8];
    const float* attn_w2 = (const float*)d_in[9];
    const float* diag_w = (const float*)d_in[10];
    float* out = (float*)d_out;

    int proj_smem = (2 * DD * ATTN + 64) * 4;                 // ~80.3 KB
    int attn_smem = (128 * 129 + LL * ATTN + ATTN * LL) * 4;  // ~117.2 KB
    cudaFuncSetAttribute(proj_kernel, cudaFuncAttributeMaxDynamicSharedMemorySize, proj_smem);
    cudaFuncSetAttribute(attn_kernel, cudaFuncAttributeMaxDynamicSharedMemorySize, attn_smem);

    full_kernel<<<BB, 128>>>(reps_lt, fw_h, bw_h, w_full, out);
    maxpool_kernel<<<dim3(BB, MPP), 256>>>(reps_lt, reps_rt, w_maxpool, out);
    proj_kernel<<<BB, 256, proj_smem>>>(reps_lt, reps_rt, attn_w1, attn_w2, diag_w);
    attn_kernel<<<BB, 256, attn_smem>>>(reps_lt);
    maxatt_kernel<<<BB, 256>>>(reps_lt, reps_rt);
    mp_elem_kernel<<<BB, 128>>>(reps_lt, reps_rt, w_att, out, 0, 41);
    mp_elem_kernel<<<BB, 128>>>(reps_lt, reps_rt, w_maxatt, out, 1, 62);
}